// round 9
// baseline (speedup 1.0000x reference)
#include <cuda_runtime.h>
#include <cuda_fp16.h>
#include <math.h>

// Problem constants
#define BB 8
#define NN 4096
#define CC 768
#define HH 8
#define DD 96
#define C3 2304
#define BH (BB*HH)
#define SPLITS 8
#define K3 1536          // 2*CC: fp16 split-K depth (A=[hi|lo], B=[hi;hi])
#define MTOT (BB*NN)     // 32768
#define NT (K3/32)       // 48 k-chunks

// Scratch (device globals — allocation-free kernel_launch)
__device__ float g_q[BB*HH*DD*NN];     // [b][h][d][n]
__device__ float g_k[BB*HH*DD*NN];
__device__ float g_v[BB*HH*DD*NN];
__device__ float g_rq[BB*HH*DD];
__device__ float g_rk[BB*HH*DD];
__device__ float g_part[SPLITS*BH*DD*DD];
__device__ float g_attn[BH*DD*DD];
__device__ float g_yt[BB*HH*DD*NN];    // y transposed: [b][c][n]

// fp16 split operands, K-MAJOR: A'[k][m]
__device__ __half g_xs[(size_t)K3*MTOT];    // GEMM1 A': rows 0..767 hi, 768..1535 lo
__device__ __half g_ys[(size_t)K3*MTOT];    // GEMM2 A'
__device__ __half g_ws[(size_t)K3*C3];      // GEMM1 B': [k][n], rows [hi;hi]
__device__ __half g_wps[(size_t)K3*CC];     // GEMM2 B'

// ---------------------------------------------------------------------------
// MMA / ldmatrix / cp.async helpers
// ---------------------------------------------------------------------------
__device__ __forceinline__ void mma16816(float* c, const unsigned* a, const unsigned* b) {
    asm volatile(
        "mma.sync.aligned.m16n8k16.row.col.f32.f16.f16.f32 "
        "{%0,%1,%2,%3}, {%4,%5,%6,%7}, {%8,%9}, {%0,%1,%2,%3};"
        : "+f"(c[0]), "+f"(c[1]), "+f"(c[2]), "+f"(c[3])
        : "r"(a[0]), "r"(a[1]), "r"(a[2]), "r"(a[3]), "r"(b[0]), "r"(b[1]));
}
__device__ __forceinline__ void ldsm_x4(unsigned* r, const void* p) {
    unsigned addr = (unsigned)__cvta_generic_to_shared(p);
    asm volatile("ldmatrix.sync.aligned.m8n8.x4.shared.b16 {%0,%1,%2,%3}, [%4];"
        : "=r"(r[0]), "=r"(r[1]), "=r"(r[2]), "=r"(r[3]) : "r"(addr));
}
__device__ __forceinline__ void ldsm_x4_t(unsigned* r, const void* p) {
    unsigned addr = (unsigned)__cvta_generic_to_shared(p);
    asm volatile("ldmatrix.sync.aligned.m8n8.x4.trans.shared.b16 {%0,%1,%2,%3}, [%4];"
        : "=r"(r[0]), "=r"(r[1]), "=r"(r[2]), "=r"(r[3]) : "r"(addr));
}
__device__ __forceinline__ void ldsm_x4_t_a(unsigned* r, unsigned addr) {
    asm volatile("ldmatrix.sync.aligned.m8n8.x4.trans.shared.b16 {%0,%1,%2,%3}, [%4];"
        : "=r"(r[0]), "=r"(r[1]), "=r"(r[2]), "=r"(r[3]) : "r"(addr));
}
__device__ __forceinline__ void cp16(const void* smem_dst, const void* gsrc) {
    unsigned d = (unsigned)__cvta_generic_to_shared(smem_dst);
    asm volatile("cp.async.cg.shared.global [%0], [%1], 16;" :: "r"(d), "l"(gsrc));
}
__device__ __forceinline__ void cp16_a(unsigned smem_dst, const void* gsrc) {
    asm volatile("cp.async.cg.shared.global [%0], [%1], 16;" :: "r"(smem_dst), "l"(gsrc));
}
#define CP_COMMIT() asm volatile("cp.async.commit_group;" ::: "memory")
#define CP_WAIT1()  asm volatile("cp.async.wait_group 1;" ::: "memory")

__device__ __forceinline__ unsigned smem_u32(const void* p) {
    return (unsigned)__cvta_generic_to_shared(p);
}
__device__ __forceinline__ void split_hl(float v, __half& hi, __half& lo) {
    hi = __float2half(v);
    lo = __float2half(v - __half2float(hi));
}
__device__ __forceinline__ void split4(float4 v, __half* h, __half* l) {
    split_hl(v.x, h[0], l[0]); split_hl(v.y, h[1], l[1]);
    split_hl(v.z, h[2], l[2]); split_hl(v.w, h[3], l[3]);
}

// ---------------------------------------------------------------------------
// split_x: x [m][c] fp32 -> g_xs [c(hi)|c+768(lo)][m] fp16 (smem transpose)
// ---------------------------------------------------------------------------
__global__ __launch_bounds__(256) void split_x_kernel(const float* __restrict__ x)
{
    __shared__ float sm[32][66];
    const int m0 = blockIdx.x * 64;
    const int c0 = blockIdx.y * 32;
    const int tx = threadIdx.x;
    const int ty = threadIdx.y;
#pragma unroll
    for (int i = 0; i < 8; i++) {
        int m = ty + i * 8;
        sm[tx][m] = x[(size_t)(m0 + m) * CC + c0 + tx];
    }
    __syncthreads();
#pragma unroll
    for (int i = 0; i < 4; i++) {
        int c = ty + i * 8;
        float v0 = sm[c][2 * tx], v1 = sm[c][2 * tx + 1];
        __half h0, l0, h1, l1;
        split_hl(v0, h0, l0); split_hl(v1, h1, l1);
        *(__half2*)&g_xs[(size_t)(c0 + c) * MTOT + m0 + 2 * tx]      = __halves2half2(h0, h1);
        *(__half2*)&g_xs[(size_t)(c0 + c + CC) * MTOT + m0 + 2 * tx] = __halves2half2(l0, l1);
    }
}

__global__ __launch_bounds__(256) void split_wqkv_kernel(const float* __restrict__ w)
{
    int idx = blockIdx.x * 256 + threadIdx.x;
    int k = idx / (C3 / 4);
    int n4 = (idx - k * (C3 / 4)) * 4;
    float4 v = *(const float4*)&w[(size_t)k * C3 + n4];
    __half hi[4];
    hi[0] = __float2half(v.x); hi[1] = __float2half(v.y);
    hi[2] = __float2half(v.z); hi[3] = __float2half(v.w);
    *(uint2*)&g_ws[(size_t)k * C3 + n4]        = *(uint2*)hi;
    *(uint2*)&g_ws[(size_t)(k + CC) * C3 + n4] = *(uint2*)hi;
}

__global__ __launch_bounds__(256) void split_wproj_kernel(const float* __restrict__ w)
{
    int idx = blockIdx.x * 256 + threadIdx.x;
    int k = idx / (CC / 4);
    int n4 = (idx - k * (CC / 4)) * 4;
    float4 v = *(const float4*)&w[(size_t)k * CC + n4];
    __half hi[4];
    hi[0] = __float2half(v.x); hi[1] = __float2half(v.y);
    hi[2] = __float2half(v.z); hi[3] = __float2half(v.w);
    *(uint2*)&g_wps[(size_t)k * CC + n4]        = *(uint2*)hi;
    *(uint2*)&g_wps[(size_t)(k + CC) * CC + n4] = *(uint2*)hi;
}

// ysplit: g_yt [b][c][n] fp32 -> g_ys [c(hi)|c+768(lo)][b*4096+n] fp16 (streaming)
__global__ __launch_bounds__(256) void ysplit_kernel()
{
    size_t idx8 = ((size_t)blockIdx.x * 256 + threadIdx.x) * 8;
    int b = (int)(idx8 / ((size_t)CC * NN));
    size_t r = idx8 - (size_t)b * CC * NN;
    int c = (int)(r / NN);
    int n = (int)(r - (size_t)c * NN);
    float4 f0 = *(const float4*)&g_yt[idx8];
    float4 f1 = *(const float4*)&g_yt[idx8 + 4];
    __half h[8], l[8];
    split4(f0, h, l); split4(f1, h + 4, l + 4);
    size_t mo = (size_t)b * NN + n;
    *(uint4*)&g_ys[(size_t)c * MTOT + mo]        = *(uint4*)h;
    *(uint4*)&g_ys[(size_t)(c + CC) * MTOT + mo] = *(uint4*)l;
}

// ---------------------------------------------------------------------------
// fp16 MMA GEMM, 3-stage cp.async pipeline, swizzled [k][*] tiles.
// All smem addresses precomputed; mainloop does stage_base + offset only.
// BM=128, BN=128, BK=32. 128 threads = 4 warps (2x2), warp tile 64x64.
// ---------------------------------------------------------------------------
#define STG_BYTES 8192   // one stage of A (or B): 32 rows x 256 B

__global__ __launch_bounds__(128, 2) void mma_gemm_kernel(
    int Ncols, int mode, const float* __restrict__ bias, float* __restrict__ out)
{
    __shared__ __align__(16) __half As[3][32][128];
    __shared__ __align__(16) __half Bs[3][32][128];
    const __half* __restrict__ A  = mode ? g_ys  : g_xs;
    const __half* __restrict__ Bm = mode ? g_wps : g_ws;

    const int tid = threadIdx.x;
    const int wid = tid >> 5, lane = tid & 31;
    const int rowBase = blockIdx.y * 128;
    const int colBase = blockIdx.x * 128;
    const int warpM = (wid & 1) * 64;
    const int warpN = (wid >> 1) * 64;

    const unsigned Abase = smem_u32(&As[0][0][0]);
    const unsigned Bbase = smem_u32(&Bs[0][0][0]);

    float acc[4][8][4] = {};

    // ---- precomputed cp.async offsets + running global pointers ----
    const int cg = tid & 15, rb = tid >> 4;
    unsigned cpoff[4];
    const __half* aSrc[4];
    const __half* bSrc[4];
#pragma unroll
    for (int p = 0; p < 4; p++) {
        int r = p * 8 + rb;
        cpoff[p] = (unsigned)(r * 256 + ((cg ^ (r & 7)) * 16));
        aSrc[p] = A  + (size_t)r * MTOT  + rowBase + cg * 8;
        bSrc[p] = Bm + (size_t)r * Ncols + colBase + cg * 8;
    }

    // ---- precomputed ldsm offsets ----
    unsigned aoff[2][4], boff[2][4];
#pragma unroll
    for (int ks = 0; ks < 2; ks++) {
        int r = ks * 16 + ((lane >> 3) & 1) * 8 + (lane & 7);
#pragma unroll
        for (int f = 0; f < 4; f++) {
            int ga = ((warpM + f * 16) >> 3) + (lane >> 4);
            int gb = ((warpN + f * 16) >> 3) + (lane >> 4);
            aoff[ks][f] = (unsigned)(r * 256 + ((ga ^ (r & 7)) * 16));
            boff[ks][f] = (unsigned)(r * 256 + ((gb ^ (r & 7)) * 16));
        }
    }

    auto load_stage = [&](int s) {
        unsigned sa = Abase + s * STG_BYTES;
        unsigned sb = Bbase + s * STG_BYTES;
#pragma unroll
        for (int p = 0; p < 4; p++) {
            cp16_a(sa + cpoff[p], aSrc[p]);
            cp16_a(sb + cpoff[p], bSrc[p]);
            aSrc[p] += (size_t)32 * MTOT;
            bSrc[p] += (size_t)32 * Ncols;
        }
        CP_COMMIT();
    };

    load_stage(0);
    load_stage(1);

    for (int t = 0; t < NT; t++) {
        CP_WAIT1();
        __syncthreads();
        if (t + 2 < NT) load_stage((t + 2) % 3);
        else            CP_COMMIT();
        const unsigned sa = Abase + (t % 3) * STG_BYTES;
        const unsigned sb = Bbase + (t % 3) * STG_BYTES;

#pragma unroll
        for (int ks = 0; ks < 2; ks++) {
            unsigned af[4][4];
#pragma unroll
            for (int im = 0; im < 4; im++) {
                unsigned r4[4];
                ldsm_x4_t_a(r4, sa + aoff[ks][im]);
                af[im][0] = r4[0]; af[im][1] = r4[2];   // reorder {r0,r2,r1,r3}
                af[im][2] = r4[1]; af[im][3] = r4[3];
            }
            unsigned bf[8][2];
#pragma unroll
            for (int gq = 0; gq < 4; gq++) {
                unsigned r4[4];
                ldsm_x4_t_a(r4, sb + boff[ks][gq]);
                bf[2 * gq][0] = r4[0]; bf[2 * gq][1] = r4[1];
                bf[2 * gq + 1][0] = r4[2]; bf[2 * gq + 1][1] = r4[3];
            }
#pragma unroll
            for (int im = 0; im < 4; im++)
#pragma unroll
                for (int jn = 0; jn < 8; jn++)
                    mma16816(acc[im][jn], af[im], bf[jn]);
        }
    }

    // Epilogue
#pragma unroll
    for (int im = 0; im < 4; im++) {
#pragma unroll
        for (int jn = 0; jn < 8; jn++) {
#pragma unroll
            for (int q = 0; q < 4; q++) {
                int m = warpM + im * 16 + (lane >> 2) + (q >> 1) * 8;
                int n = warpN + jn * 8 + (lane & 3) * 2 + (q & 1);
                float val = acc[im][jn][q];
                int row = rowBase + m;
                int col = colBase + n;
                if (mode == 0) {
                    int b = row >> 12;
                    int nn2 = row & 4095;
                    int h = col / 288;
                    int rem = col - h * 288;
                    int d = rem / 3;
                    int s3 = rem - d * 3;
                    float* dst = (s3 == 0) ? g_q : (s3 == 1) ? g_k : g_v;
                    dst[((b * HH + h) * DD + d) * NN + nn2] = val;
                } else {
                    out[(size_t)row * CC + col] = val + bias[col];
                }
            }
        }
    }
}

// ---------------------------------------------------------------------------
// norm: per-(b,h,d) inverse L2 norm over N for q (y=0) and k (y=1)
// ---------------------------------------------------------------------------
__global__ __launch_bounds__(256) void norm_kernel()
{
    const int row = blockIdx.x;
    const float* src = (blockIdx.y == 0) ? g_q : g_k;
    float*       dst = (blockIdx.y == 0) ? g_rq : g_rk;
    const float* p = src + (size_t)row * NN;
    float s = 0.f;
    for (int i = threadIdx.x; i < NN; i += 256) {
        float v = p[i];
        s = fmaf(v, v, s);
    }
#pragma unroll
    for (int off = 16; off; off >>= 1) s += __shfl_down_sync(0xffffffffu, s, off);
    __shared__ float ws[8];
    if ((threadIdx.x & 31) == 0) ws[threadIdx.x >> 5] = s;
    __syncthreads();
    if (threadIdx.x < 8) {
        float t = ws[threadIdx.x];
#pragma unroll
        for (int off = 4; off; off >>= 1) t += __shfl_down_sync(0xffu, t, off);
        if (threadIdx.x == 0) dst[row] = rsqrtf(t);
    }
}

// ---------------------------------------------------------------------------
// attn_part (tensor MMA): part[sp][bh][d][e] = sum_n q[d,n]k[e,n]
// ---------------------------------------------------------------------------
__global__ __launch_bounds__(128) void attn_part_kernel()
{
    __shared__ __align__(16) __half Qs[2][96][40];
    __shared__ __align__(16) __half Ks[2][96][40];
    const int tid = threadIdx.x;
    const int wid = tid >> 5, lane = tid & 31;
    const int bh = blockIdx.x;
    const int n0 = blockIdx.y * (NN / SPLITS);
    const float* qp = g_q + (size_t)bh * DD * NN;
    const float* kp = g_k + (size_t)bh * DD * NN;
    const int warpM = (wid & 1) * 48, warpN = (wid >> 1) * 48;

    float acc[3][6][4] = {};

    for (int nc = 0; nc < NN / SPLITS; nc += 32) {
        if (nc) __syncthreads();
#pragma unroll
        for (int p = 0; p < 6; p++) {
            int idx = p * 128 + tid;
            int r = idx >> 3, c4 = (idx & 7) * 4;
            float4 qv = *(const float4*)&qp[(size_t)r * NN + n0 + nc + c4];
            float4 kv = *(const float4*)&kp[(size_t)r * NN + n0 + nc + c4];
            __half qh[4], ql[4], kh[4], kl[4];
            split4(qv, qh, ql); split4(kv, kh, kl);
            *(uint2*)&Qs[0][r][c4] = *(uint2*)qh;
            *(uint2*)&Qs[1][r][c4] = *(uint2*)ql;
            *(uint2*)&Ks[0][r][c4] = *(uint2*)kh;
            *(uint2*)&Ks[1][r][c4] = *(uint2*)kl;
        }
        __syncthreads();
#pragma unroll
        for (int term = 0; term < 3; term++) {
            const __half (*Aq)[40] = (term == 1) ? Qs[1] : Qs[0];
            const __half (*Bk)[40] = (term == 2) ? Ks[1] : Ks[0];
#pragma unroll
            for (int ks = 0; ks < 2; ks++) {
                unsigned af[3][4];
#pragma unroll
                for (int im = 0; im < 3; im++)
                    ldsm_x4(af[im], &Aq[warpM + im * 16 + (lane & 15)]
                                       [ks * 16 + (lane >> 4) * 8]);
                unsigned bf[6][2];
#pragma unroll
                for (int jg = 0; jg < 3; jg++) {
                    unsigned r4[4];
                    ldsm_x4(r4, &Bk[warpN + jg * 16 + (lane & 15)]
                                   [ks * 16 + (lane >> 4) * 8]);
                    bf[2 * jg][0] = r4[0]; bf[2 * jg][1] = r4[2];
                    bf[2 * jg + 1][0] = r4[1]; bf[2 * jg + 1][1] = r4[3];
                }
#pragma unroll
                for (int im = 0; im < 3; im++)
#pragma unroll
                    for (int jn = 0; jn < 6; jn++)
                        mma16816(acc[im][jn], af[im], bf[jn]);
            }
        }
    }

    float* dst = g_part + ((size_t)blockIdx.y * BH + bh) * DD * DD;
#pragma unroll
    for (int im = 0; im < 3; im++)
#pragma unroll
        for (int jn = 0; jn < 6; jn++)
#pragma unroll
            for (int q = 0; q < 4; q++) {
                int row = warpM + im * 16 + (lane >> 2) + (q >> 1) * 8;
                int col = warpN + jn * 8 + (lane & 3) * 2 + (q & 1);
                dst[row * DD + col] = acc[im][jn][q];
            }
}

// ---------------------------------------------------------------------------
// softmax: reduce split-K partials, apply norms * temp, softmax over e.
// ---------------------------------------------------------------------------
__global__ __launch_bounds__(128) void softmax_kernel(const float* __restrict__ temp)
{
    const int bhd = blockIdx.x;
    const int bh = bhd / DD;
    const int d  = bhd - bh * DD;
    const int h  = bh & (HH - 1);
    const int e  = threadIdx.x;

    float raw = 0.f;
    float val = -1e30f;
    if (e < DD) {
        float s = 0.f;
#pragma unroll
        for (int sp = 0; sp < SPLITS; sp++)
            s += g_part[(((size_t)sp * BH + bh) * DD + d) * DD + e];
        raw = s * g_rq[bh * DD + d] * g_rk[bh * DD + e] * temp[h];
        val = raw;
    }

    __shared__ float red[128];
    red[e] = val;
    __syncthreads();
#pragma unroll
    for (int off = 64; off >= 1; off >>= 1) {
        if (e < off) red[e] = fmaxf(red[e], red[e + off]);
        __syncthreads();
    }
    float m = red[0];
    __syncthreads();

    float ex = (e < DD) ? expf(raw - m) : 0.f;
    red[e] = ex;
    __syncthreads();
#pragma unroll
    for (int off = 64; off >= 1; off >>= 1) {
        if (e < off) red[e] += red[e + off];
        __syncthreads();
    }
    float sum = red[0];

    if (e < DD)
        g_attn[((size_t)bh * DD + d) * DD + e] = ex / sum;
}

// ---------------------------------------------------------------------------
// av (tensor MMA): y_t[d][n] = sum_e attn[d][e] * v[e][n]
// ---------------------------------------------------------------------------
__global__ __launch_bounds__(128) void av_kernel()
{
    __shared__ __align__(16) __half Ah[2][96][104];
    __shared__ __align__(16) __half Vs[2][16][136];
    const int tid = threadIdx.x;
    const int wid = tid >> 5, lane = tid & 31;
    const int bh = blockIdx.x;
    const int n0 = blockIdx.y * 128;
    const float* ap = g_attn + (size_t)bh * DD * DD;
    const float* vp = g_v + (size_t)bh * DD * NN;
    const int warpM = (wid & 1) * 48, warpN = (wid >> 1) * 64;

    float acc[3][8][4] = {};

#pragma unroll
    for (int p = 0; p < 18; p++) {
        int idx = p * 128 + tid;
        int r = idx / 24, c4 = (idx % 24) * 4;
        float4 v = *(const float4*)&ap[r * DD + c4];
        __half h[4], l[4];
        split4(v, h, l);
        *(uint2*)&Ah[0][r][c4] = *(uint2*)h;
        *(uint2*)&Ah[1][r][c4] = *(uint2*)l;
    }

    for (int ec = 0; ec < DD; ec += 16) {
        __syncthreads();
#pragma unroll
        for (int p = 0; p < 4; p++) {
            int idx = p * 128 + tid;
            int r = idx >> 5, c4 = (idx & 31) * 4;
            float4 vv = *(const float4*)&vp[(size_t)(ec + r) * NN + n0 + c4];
            __half h[4], l[4];
            split4(vv, h, l);
            *(uint2*)&Vs[0][r][c4] = *(uint2*)h;
            *(uint2*)&Vs[1][r][c4] = *(uint2*)l;
        }
        __syncthreads();
#pragma unroll
        for (int term = 0; term < 3; term++) {
            const __half (*Aa)[104] = (term == 1) ? Ah[1] : Ah[0];
            const __half (*Vv)[136] = (term == 2) ? Vs[1] : Vs[0];
            unsigned af[3][4];
#pragma unroll
            for (int im = 0; im < 3; im++)
                ldsm_x4(af[im], &Aa[warpM + im * 16 + (lane & 15)]
                                   [ec + (lane >> 4) * 8]);
            unsigned bf[8][2];
#pragma unroll
            for (int g = 0; g < 4; g++) {
                unsigned r4[4];
                ldsm_x4_t(r4, &Vv[((lane >> 3) & 1) * 8 + (lane & 7)]
                              [warpN + g * 16 + (lane >> 4) * 8]);
                bf[2 * g][0] = r4[0]; bf[2 * g][1] = r4[1];
                bf[2 * g + 1][0] = r4[2]; bf[2 * g + 1][1] = r4[3];
            }
#pragma unroll
            for (int im = 0; im < 3; im++)
#pragma unroll
                for (int jn = 0; jn < 8; jn++)
                    mma16816(acc[im][jn], af[im], bf[jn]);
        }
    }

    float* yp = g_yt + (size_t)bh * DD * NN;
#pragma unroll
    for (int im = 0; im < 3; im++)
#pragma unroll
        for (int jn = 0; jn < 8; jn++)
#pragma unroll
            for (int q = 0; q < 4; q++) {
                int row = warpM + im * 16 + (lane >> 2) + (q >> 1) * 8;
                int col = warpN + jn * 8 + (lane & 3) * 2 + (q & 1);
                yp[(size_t)row * NN + n0 + col] = acc[im][jn][q];
            }
}

// ---------------------------------------------------------------------------
extern "C" void kernel_launch(void* const* d_in, const int* in_sizes, int n_in,
                              void* d_out, int out_size)
{
    const float* x      = (const float*)d_in[0];
    const float* w_qkv  = (const float*)d_in[1];
    const float* w_proj = (const float*)d_in[2];
    const float* b_proj = (const float*)d_in[3];
    const float* temp   = (const float*)d_in[4];
    float* out = (float*)d_out;

    split_x_kernel<<<dim3(MTOT / 64, CC / 32), dim3(32, 8)>>>(x);
    split_wqkv_kernel<<<(CC * C3 / 4) / 256, 256>>>(w_qkv);
    split_wproj_kernel<<<(CC * CC / 4) / 256, 256>>>(w_proj);

    // GEMM1: scatter q/k/v
    mma_gemm_kernel<<<dim3(C3 / 128, MTOT / 128), 128>>>(C3, 0, nullptr, nullptr);

    norm_kernel<<<dim3(BH * DD, 2), 256>>>();
    attn_part_kernel<<<dim3(BH, SPLITS), 128>>>();
    softmax_kernel<<<BH * DD, 128>>>(temp);
    av_kernel<<<dim3(BH, NN / 128), 128>>>();

    ysplit_kernel<<<(BB * CC * NN / 8) / 256, 256>>>();

    // GEMM2: out = y @ W_proj + bias
    mma_gemm_kernel<<<dim3(CC / 128, MTOT / 128), 128>>>(CC, 1, b_proj, out);
}

// round 10
// speedup vs baseline: 1.6600x; 1.6600x over previous
#include <cuda_runtime.h>
#include <cuda_fp16.h>
#include <math.h>

// Problem constants
#define BB 8
#define NN 4096
#define CC 768
#define HH 8
#define DD 96
#define C3 2304
#define BH (BB*HH)
#define SPLITS 8
#define K3 1536   // 2*CC: fp16 split-K depth (A=[hi|lo], B=[hi;hi])
#define MTOT (BB*NN)

// Scratch (device globals — allocation-free kernel_launch)
__device__ float g_q[BB*HH*DD*NN];     // [b][h][d][n]
__device__ float g_k[BB*HH*DD*NN];
__device__ float g_v[BB*HH*DD*NN];
__device__ float g_rq[BB*HH*DD];
__device__ float g_rk[BB*HH*DD];
__device__ float g_part[SPLITS*BH*DD*DD];
__device__ float g_attn[BH*DD*DD];
__device__ float g_yt[BB*HH*DD*NN];    // y transposed: [b][c][n]

// fp16 split operands, M-MAJOR rows: A'[m][k]
__device__ __half g_xs[(size_t)MTOT*K3];    // GEMM1 A': [m][hi|lo]
__device__ __half g_ys[(size_t)MTOT*K3];    // GEMM2 A'
__device__ __half g_ws[(size_t)K3*C3];      // GEMM1 B': [k][n] rows [hi;hi]
__device__ __half g_wps[(size_t)K3*CC];     // GEMM2 B'

// ---------------------------------------------------------------------------
// MMA / ldmatrix / cp.async helpers
// ---------------------------------------------------------------------------
__device__ __forceinline__ void mma16816(float* c, const unsigned* a, const unsigned* b) {
    asm volatile(
        "mma.sync.aligned.m16n8k16.row.col.f32.f16.f16.f32 "
        "{%0,%1,%2,%3}, {%4,%5,%6,%7}, {%8,%9}, {%0,%1,%2,%3};"
        : "+f"(c[0]), "+f"(c[1]), "+f"(c[2]), "+f"(c[3])
        : "r"(a[0]), "r"(a[1]), "r"(a[2]), "r"(a[3]), "r"(b[0]), "r"(b[1]));
}
__device__ __forceinline__ void ldsm_x4(unsigned* r, const void* p) {
    unsigned addr = (unsigned)__cvta_generic_to_shared(p);
    asm volatile("ldmatrix.sync.aligned.m8n8.x4.shared.b16 {%0,%1,%2,%3}, [%4];"
        : "=r"(r[0]), "=r"(r[1]), "=r"(r[2]), "=r"(r[3]) : "r"(addr));
}
__device__ __forceinline__ void ldsm_x4_t(unsigned* r, const void* p) {
    unsigned addr = (unsigned)__cvta_generic_to_shared(p);
    asm volatile("ldmatrix.sync.aligned.m8n8.x4.trans.shared.b16 {%0,%1,%2,%3}, [%4];"
        : "=r"(r[0]), "=r"(r[1]), "=r"(r[2]), "=r"(r[3]) : "r"(addr));
}
__device__ __forceinline__ void cp16(const void* smem_dst, const void* gsrc) {
    unsigned d = (unsigned)__cvta_generic_to_shared(smem_dst);
    asm volatile("cp.async.cg.shared.global [%0], [%1], 16;" :: "r"(d), "l"(gsrc));
}
#define CP_COMMIT() asm volatile("cp.async.commit_group;" ::: "memory")
#define CP_WAIT0()  asm volatile("cp.async.wait_group 0;" ::: "memory")

__device__ __forceinline__ void split_hl(float v, __half& hi, __half& lo) {
    hi = __float2half(v);
    lo = __float2half(v - __half2float(hi));
}
__device__ __forceinline__ void split4(float4 v, __half* h, __half* l) {
    split_hl(v.x, h[0], l[0]); split_hl(v.y, h[1], l[1]);
    split_hl(v.z, h[2], l[2]); split_hl(v.w, h[3], l[3]);
}

// ---------------------------------------------------------------------------
// Split kernels (R7-proven): A rows m-major [hi|lo]; W rows [hi;hi]
// ---------------------------------------------------------------------------
__global__ __launch_bounds__(256) void split_x_kernel(const float* __restrict__ x)
{
    int idx = blockIdx.x * 256 + threadIdx.x;
    int m = idx / (CC / 4);
    int k4 = (idx - m * (CC / 4)) * 4;
    float4 v = *(const float4*)&x[(size_t)m * CC + k4];
    __half hi[4], lo[4];
    split4(v, hi, lo);
    __half* base = g_xs + (size_t)m * K3 + k4;
    *(uint2*)(base)      = *(uint2*)hi;
    *(uint2*)(base + CC) = *(uint2*)lo;
}

__global__ __launch_bounds__(256) void split_wqkv_kernel(const float* __restrict__ w)
{
    int idx = blockIdx.x * 256 + threadIdx.x;
    int k = idx / (C3 / 4);
    int n4 = (idx - k * (C3 / 4)) * 4;
    float4 v = *(const float4*)&w[(size_t)k * C3 + n4];
    __half hi[4];
    hi[0] = __float2half(v.x); hi[1] = __float2half(v.y);
    hi[2] = __float2half(v.z); hi[3] = __float2half(v.w);
    *(uint2*)&g_ws[(size_t)k * C3 + n4]        = *(uint2*)hi;
    *(uint2*)&g_ws[(size_t)(k + CC) * C3 + n4] = *(uint2*)hi;
}

__global__ __launch_bounds__(256) void split_wproj_kernel(const float* __restrict__ w)
{
    int idx = blockIdx.x * 256 + threadIdx.x;
    int k = idx / (CC / 4);
    int n4 = (idx - k * (CC / 4)) * 4;
    float4 v = *(const float4*)&w[(size_t)k * CC + n4];
    __half hi[4];
    hi[0] = __float2half(v.x); hi[1] = __float2half(v.y);
    hi[2] = __float2half(v.z); hi[3] = __float2half(v.w);
    *(uint2*)&g_wps[(size_t)k * CC + n4]        = *(uint2*)hi;
    *(uint2*)&g_wps[(size_t)(k + CC) * CC + n4] = *(uint2*)hi;
}

// Transpose g_yt [b][c][n] f32 -> g_ys [b*N+n][hi|lo over c] fp16
__global__ __launch_bounds__(256) void ysplit_kernel()
{
    __shared__ float sm[32][33];
    const int n0 = blockIdx.x * 32;
    const int c0 = blockIdx.y * 32;
    const int b  = blockIdx.z;
    const int tx = threadIdx.x, ty = threadIdx.y;   // 32 x 8
#pragma unroll
    for (int i = 0; i < 4; i++) {
        int c = c0 + ty + i * 8;
        sm[ty + i * 8][tx] = g_yt[((size_t)b * CC + c) * NN + n0 + tx];
    }
    __syncthreads();
#pragma unroll
    for (int i = 0; i < 4; i++) {
        int n = n0 + ty + i * 8;
        int c = c0 + tx;
        __half hi, lo;
        split_hl(sm[tx][ty + i * 8], hi, lo);
        __half* base = g_ys + ((size_t)b * NN + n) * K3;
        base[c]      = hi;
        base[CC + c] = lo;
    }
}

// ---------------------------------------------------------------------------
// fp16 MMA GEMM (R7-proven): BM=128, BN=128, BK=32. 128 thr = 4 warps (2x2),
// warp tile 64x64. cp.async double-buffer, 2 CTAs/SM.
// mode 0: scatter into g_q/g_k/g_v.  mode 1: out = C + bias.
// ---------------------------------------------------------------------------
__global__ __launch_bounds__(128, 2) void mma_gemm_kernel(
    int Ncols, int mode, const float* __restrict__ bias, float* __restrict__ out)
{
    __shared__ __align__(16) __half As[2][128][40];   // stride 40: ldsm conflict-free
    __shared__ __align__(16) __half Bs[2][32][136];   // stride 136: ldsm conflict-free
    const __half* __restrict__ A  = mode ? g_ys  : g_xs;
    const __half* __restrict__ Bm = mode ? g_wps : g_ws;

    const int tid = threadIdx.x;
    const int wid = tid >> 5, lane = tid & 31;
    const int rowBase = blockIdx.y * 128;
    const int colBase = blockIdx.x * 128;
    const int warpM = (wid & 1) * 64;
    const int warpN = (wid >> 1) * 64;

    float acc[4][8][4] = {};

    const int ar = tid >> 2, ac = (tid & 3) * 8;      // A: 4 passes (+32 rows)
    const int br = tid >> 4, bc2 = (tid & 15) * 8;    // B: 4 passes (+8 rows)

    const __half* aptr = A  + (size_t)(rowBase + ar) * K3 + ac;
    const __half* bptr = Bm + (size_t)br * Ncols + colBase + bc2;

    // prologue: prefetch chunk 0 -> buf 0
#pragma unroll
    for (int p = 0; p < 4; p++)
        cp16(&As[0][ar + p * 32][ac], aptr + (size_t)p * 32 * K3);
#pragma unroll
    for (int p = 0; p < 4; p++)
        cp16(&Bs[0][br + p * 8][bc2], bptr + (size_t)p * 8 * Ncols);
    CP_COMMIT();

    const int NT = K3 / 32;
    for (int t = 0; t < NT; t++) {
        const int buf = t & 1;
        CP_WAIT0();
        __syncthreads();

        if (t + 1 < NT) {
            const int k0 = (t + 1) * 32;
            const int nb = buf ^ 1;
#pragma unroll
            for (int p = 0; p < 4; p++)
                cp16(&As[nb][ar + p * 32][ac], aptr + (size_t)p * 32 * K3 + k0);
#pragma unroll
            for (int p = 0; p < 4; p++)
                cp16(&Bs[nb][br + p * 8][bc2], bptr + ((size_t)k0 + p * 8) * Ncols);
            CP_COMMIT();
        }

#pragma unroll
        for (int ks = 0; ks < 2; ks++) {
            unsigned af[4][4];
#pragma unroll
            for (int im = 0; im < 4; im++)
                ldsm_x4(af[im], &As[buf][warpM + im * 16 + (lane & 15)]
                                   [ks * 16 + (lane >> 4) * 8]);
            unsigned bf[8][2];
#pragma unroll
            for (int g = 0; g < 4; g++) {
                unsigned r[4];
                ldsm_x4_t(r, &Bs[buf][ks * 16 + ((lane >> 3) & 1) * 8 + (lane & 7)]
                             [warpN + g * 16 + (lane >> 4) * 8]);
                bf[2 * g][0] = r[0]; bf[2 * g][1] = r[1];
                bf[2 * g + 1][0] = r[2]; bf[2 * g + 1][1] = r[3];
            }
#pragma unroll
            for (int im = 0; im < 4; im++)
#pragma unroll
                for (int jn = 0; jn < 8; jn++)
                    mma16816(acc[im][jn], af[im], bf[jn]);
        }
    }

    // Epilogue
#pragma unroll
    for (int im = 0; im < 4; im++) {
#pragma unroll
        for (int jn = 0; jn < 8; jn++) {
#pragma unroll
            for (int q = 0; q < 4; q++) {
                int m = warpM + im * 16 + (lane >> 2) + (q >> 1) * 8;
                int n = warpN + jn * 8 + (lane & 3) * 2 + (q & 1);
                float val = acc[im][jn][q];
                int row = rowBase + m;
                int col = colBase + n;
                if (mode == 0) {
                    int b = row >> 12;
                    int nn2 = row & 4095;
                    int h = col / 288;
                    int rem = col - h * 288;
                    int d = rem / 3;
                    int s = rem - d * 3;
                    float* dst = (s == 0) ? g_q : (s == 1) ? g_k : g_v;
                    dst[((b * HH + h) * DD + d) * NN + nn2] = val;
                } else {
                    out[(size_t)row * CC + col] = val + bias[col];
                }
            }
        }
    }
}

// ---------------------------------------------------------------------------
// norm: per-(b,h,d) inverse L2 norm over N for q (y=0) and k (y=1)
// ---------------------------------------------------------------------------
__global__ __launch_bounds__(256) void norm_kernel()
{
    const int row = blockIdx.x;
    const float* src = (blockIdx.y == 0) ? g_q : g_k;
    float*       dst = (blockIdx.y == 0) ? g_rq : g_rk;
    const float* p = src + (size_t)row * NN;
    float s = 0.f;
    for (int i = threadIdx.x; i < NN; i += 256) {
        float v = p[i];
        s = fmaf(v, v, s);
    }
#pragma unroll
    for (int off = 16; off; off >>= 1) s += __shfl_down_sync(0xffffffffu, s, off);
    __shared__ float ws[8];
    if ((threadIdx.x & 31) == 0) ws[threadIdx.x >> 5] = s;
    __syncthreads();
    if (threadIdx.x < 8) {
        float t = ws[threadIdx.x];
#pragma unroll
        for (int off = 4; off; off >>= 1) t += __shfl_down_sync(0xffu, t, off);
        if (threadIdx.x == 0) dst[row] = rsqrtf(t);
    }
}

// ---------------------------------------------------------------------------
// attn_part (tensor MMA, R8-proven): part[sp][bh][d][e] = sum_n q[d,n]k[e,n]
// ---------------------------------------------------------------------------
__global__ __launch_bounds__(128) void attn_part_kernel()
{
    __shared__ __align__(16) __half Qs[2][96][40];
    __shared__ __align__(16) __half Ks[2][96][40];
    const int tid = threadIdx.x;
    const int wid = tid >> 5, lane = tid & 31;
    const int bh = blockIdx.x;
    const int n0 = blockIdx.y * (NN / SPLITS);
    const float* qp = g_q + (size_t)bh * DD * NN;
    const float* kp = g_k + (size_t)bh * DD * NN;
    const int warpM = (wid & 1) * 48, warpN = (wid >> 1) * 48;

    float acc[3][6][4] = {};

    for (int nc = 0; nc < NN / SPLITS; nc += 32) {
        if (nc) __syncthreads();
#pragma unroll
        for (int p = 0; p < 6; p++) {
            int idx = p * 128 + tid;
            int r = idx >> 3, c4 = (idx & 7) * 4;
            float4 qv = *(const float4*)&qp[(size_t)r * NN + n0 + nc + c4];
            float4 kv = *(const float4*)&kp[(size_t)r * NN + n0 + nc + c4];
            __half qh[4], ql[4], kh[4], kl[4];
            split4(qv, qh, ql); split4(kv, kh, kl);
            *(uint2*)&Qs[0][r][c4] = *(uint2*)qh;
            *(uint2*)&Qs[1][r][c4] = *(uint2*)ql;
            *(uint2*)&Ks[0][r][c4] = *(uint2*)kh;
            *(uint2*)&Ks[1][r][c4] = *(uint2*)kl;
        }
        __syncthreads();
#pragma unroll
        for (int term = 0; term < 3; term++) {
            const __half (*Aq)[40] = (term == 1) ? Qs[1] : Qs[0];
            const __half (*Bk)[40] = (term == 2) ? Ks[1] : Ks[0];
#pragma unroll
            for (int ks = 0; ks < 2; ks++) {
                unsigned af[3][4];
#pragma unroll
                for (int im = 0; im < 3; im++)
                    ldsm_x4(af[im], &Aq[warpM + im * 16 + (lane & 15)]
                                       [ks * 16 + (lane >> 4) * 8]);
                unsigned bf[6][2];
#pragma unroll
                for (int jg = 0; jg < 3; jg++) {
                    unsigned r4[4];
                    ldsm_x4(r4, &Bk[warpN + jg * 16 + (lane & 15)]
                                   [ks * 16 + (lane >> 4) * 8]);
                    bf[2 * jg][0] = r4[0]; bf[2 * jg][1] = r4[2];
                    bf[2 * jg + 1][0] = r4[1]; bf[2 * jg + 1][1] = r4[3];
                }
#pragma unroll
                for (int im = 0; im < 3; im++)
#pragma unroll
                    for (int jn = 0; jn < 6; jn++)
                        mma16816(acc[im][jn], af[im], bf[jn]);
            }
        }
    }

    float* dst = g_part + ((size_t)blockIdx.y * BH + bh) * DD * DD;
#pragma unroll
    for (int im = 0; im < 3; im++)
#pragma unroll
        for (int jn = 0; jn < 6; jn++)
#pragma unroll
            for (int q = 0; q < 4; q++) {
                int row = warpM + im * 16 + (lane >> 2) + (q >> 1) * 8;
                int col = warpN + jn * 8 + (lane & 3) * 2 + (q & 1);
                dst[row * DD + col] = acc[im][jn][q];
            }
}

// ---------------------------------------------------------------------------
// softmax: reduce split-K partials, apply norms * temp, softmax over e.
// ---------------------------------------------------------------------------
__global__ __launch_bounds__(128) void softmax_kernel(const float* __restrict__ temp)
{
    const int bhd = blockIdx.x;
    const int bh = bhd / DD;
    const int d  = bhd - bh * DD;
    const int h  = bh & (HH - 1);
    const int e  = threadIdx.x;

    float raw = 0.f;
    float val = -1e30f;
    if (e < DD) {
        float s = 0.f;
#pragma unroll
        for (int sp = 0; sp < SPLITS; sp++)
            s += g_part[(((size_t)sp * BH + bh) * DD + d) * DD + e];
        raw = s * g_rq[bh * DD + d] * g_rk[bh * DD + e] * temp[h];
        val = raw;
    }

    __shared__ float red[128];
    red[e] = val;
    __syncthreads();
#pragma unroll
    for (int off = 64; off >= 1; off >>= 1) {
        if (e < off) red[e] = fmaxf(red[e], red[e + off]);
        __syncthreads();
    }
    float m = red[0];
    __syncthreads();

    float ex = (e < DD) ? expf(raw - m) : 0.f;
    red[e] = ex;
    __syncthreads();
#pragma unroll
    for (int off = 64; off >= 1; off >>= 1) {
        if (e < off) red[e] += red[e + off];
        __syncthreads();
    }
    float sum = red[0];

    if (e < DD)
        g_attn[((size_t)bh * DD + d) * DD + e] = ex / sum;
}

// ---------------------------------------------------------------------------
// av (tensor MMA, R8-proven): y_t[d][n] = sum_e attn[d][e] * v[e][n]
// ---------------------------------------------------------------------------
__global__ __launch_bounds__(128) void av_kernel()
{
    __shared__ __align__(16) __half Ah[2][96][104];
    __shared__ __align__(16) __half Vs[2][16][136];
    const int tid = threadIdx.x;
    const int wid = tid >> 5, lane = tid & 31;
    const int bh = blockIdx.x;
    const int n0 = blockIdx.y * 128;
    const float* ap = g_attn + (size_t)bh * DD * DD;
    const float* vp = g_v + (size_t)bh * DD * NN;
    const int warpM = (wid & 1) * 48, warpN = (wid >> 1) * 64;

    float acc[3][8][4] = {};

#pragma unroll
    for (int p = 0; p < 18; p++) {
        int idx = p * 128 + tid;
        int r = idx / 24, c4 = (idx % 24) * 4;
        float4 v = *(const float4*)&ap[r * DD + c4];
        __half h[4], l[4];
        split4(v, h, l);
        *(uint2*)&Ah[0][r][c4] = *(uint2*)h;
        *(uint2*)&Ah[1][r][c4] = *(uint2*)l;
    }

    for (int ec = 0; ec < DD; ec += 16) {
        __syncthreads();
#pragma unroll
        for (int p = 0; p < 4; p++) {
            int idx = p * 128 + tid;
            int r = idx >> 5, c4 = (idx & 31) * 4;
            float4 vv = *(const float4*)&vp[(size_t)(ec + r) * NN + n0 + c4];
            __half h[4], l[4];
            split4(vv, h, l);
            *(uint2*)&Vs[0][r][c4] = *(uint2*)h;
            *(uint2*)&Vs[1][r][c4] = *(uint2*)l;
        }
        __syncthreads();
#pragma unroll
        for (int term = 0; term < 3; term++) {
            const __half (*Aa)[104] = (term == 1) ? Ah[1] : Ah[0];
            const __half (*Vv)[136] = (term == 2) ? Vs[1] : Vs[0];
            unsigned af[3][4];
#pragma unroll
            for (int im = 0; im < 3; im++)
                ldsm_x4(af[im], &Aa[warpM + im * 16 + (lane & 15)]
                                   [ec + (lane >> 4) * 8]);
            unsigned bf[8][2];
#pragma unroll
            for (int g = 0; g < 4; g++) {
                unsigned r4[4];
                ldsm_x4_t(r4, &Vv[((lane >> 3) & 1) * 8 + (lane & 7)]
                              [warpN + g * 16 + (lane >> 4) * 8]);
                bf[2 * g][0] = r4[0]; bf[2 * g][1] = r4[1];
                bf[2 * g + 1][0] = r4[2]; bf[2 * g + 1][1] = r4[3];
            }
#pragma unroll
            for (int im = 0; im < 3; im++)
#pragma unroll
                for (int jn = 0; jn < 8; jn++)
                    mma16816(acc[im][jn], af[im], bf[jn]);
        }
    }

    float* yp = g_yt + (size_t)bh * DD * NN;
#pragma unroll
    for (int im = 0; im < 3; im++)
#pragma unroll
        for (int jn = 0; jn < 8; jn++)
#pragma unroll
            for (int q = 0; q < 4; q++) {
                int row = warpM + im * 16 + (lane >> 2) + (q >> 1) * 8;
                int col = warpN + jn * 8 + (lane & 3) * 2 + (q & 1);
                yp[(size_t)row * NN + n0 + col] = acc[im][jn][q];
            }
}

// ---------------------------------------------------------------------------
extern "C" void kernel_launch(void* const* d_in, const int* in_sizes, int n_in,
                              void* d_out, int out_size)
{
    const float* x      = (const float*)d_in[0];
    const float* w_qkv  = (const float*)d_in[1];
    const float* w_proj = (const float*)d_in[2];
    const float* b_proj = (const float*)d_in[3];
    const float* temp   = (const float*)d_in[4];
    float* out = (float*)d_out;

    split_x_kernel<<<(MTOT * CC / 4) / 256, 256>>>(x);
    split_wqkv_kernel<<<(CC * C3 / 4) / 256, 256>>>(w_qkv);
    split_wproj_kernel<<<(CC * CC / 4) / 256, 256>>>(w_proj);

    // GEMM1: scatter q/k/v
    mma_gemm_kernel<<<dim3(C3 / 128, MTOT / 128), 128>>>(C3, 0, nullptr, nullptr);

    norm_kernel<<<dim3(BH * DD, 2), 256>>>();
    attn_part_kernel<<<dim3(BH, SPLITS), 128>>>();
    softmax_kernel<<<BH * DD, 128>>>(temp);
    av_kernel<<<dim3(BH, NN / 128), 128>>>();

    ysplit_kernel<<<dim3(NN / 32, CC / 32, BB), dim3(32, 8)>>>();

    // GEMM2: out = y @ W_proj + bias
    mma_gemm_kernel<<<dim3(CC / 128, MTOT / 128), 128>>>(CC, 1, b_proj, out);
}

// round 11
// speedup vs baseline: 1.7444x; 1.0509x over previous
#include <cuda_runtime.h>
#include <cuda_fp16.h>
#include <math.h>

// Problem constants
#define BB 8
#define NN 4096
#define CC 768
#define HH 8
#define DD 96
#define C3 2304
#define BH (BB*HH)
#define SPLITS 8
#define K3 1536   // 2*CC: fp16 split-K depth (A=[hi|lo], B=[hi;hi])
#define MTOT (BB*NN)

// Scratch (device globals — allocation-free kernel_launch)
__device__ float g_q[BB*HH*DD*NN];     // [b][h][d][n]
__device__ float g_k[BB*HH*DD*NN];
__device__ float g_v[BB*HH*DD*NN];
__device__ float g_rq[BB*HH*DD];
__device__ float g_rk[BB*HH*DD];
__device__ float g_part[SPLITS*BH*DD*DD];
__device__ float g_attn[BH*DD*DD];
__device__ float g_yt[BB*HH*DD*NN];    // y transposed: [b][c][n]

// fp16 split operands, M-MAJOR rows: A'[m][k]
__device__ __half g_xs[(size_t)MTOT*K3];    // GEMM1 A': [m][hi|lo]
__device__ __half g_ys[(size_t)MTOT*K3];    // GEMM2 A'
__device__ __half g_ws[(size_t)K3*C3];      // GEMM1 B': [k][n] rows [hi;hi]
__device__ __half g_wps[(size_t)K3*CC];     // GEMM2 B'

// ---------------------------------------------------------------------------
// MMA / ldmatrix / cp.async helpers
// ---------------------------------------------------------------------------
__device__ __forceinline__ void mma16816(float* c, const unsigned* a, const unsigned* b) {
    asm volatile(
        "mma.sync.aligned.m16n8k16.row.col.f32.f16.f16.f32 "
        "{%0,%1,%2,%3}, {%4,%5,%6,%7}, {%8,%9}, {%0,%1,%2,%3};"
        : "+f"(c[0]), "+f"(c[1]), "+f"(c[2]), "+f"(c[3])
        : "r"(a[0]), "r"(a[1]), "r"(a[2]), "r"(a[3]), "r"(b[0]), "r"(b[1]));
}
__device__ __forceinline__ void ldsm_x4(unsigned* r, const void* p) {
    unsigned addr = (unsigned)__cvta_generic_to_shared(p);
    asm volatile("ldmatrix.sync.aligned.m8n8.x4.shared.b16 {%0,%1,%2,%3}, [%4];"
        : "=r"(r[0]), "=r"(r[1]), "=r"(r[2]), "=r"(r[3]) : "r"(addr));
}
__device__ __forceinline__ void ldsm_x4_t(unsigned* r, const void* p) {
    unsigned addr = (unsigned)__cvta_generic_to_shared(p);
    asm volatile("ldmatrix.sync.aligned.m8n8.x4.trans.shared.b16 {%0,%1,%2,%3}, [%4];"
        : "=r"(r[0]), "=r"(r[1]), "=r"(r[2]), "=r"(r[3]) : "r"(addr));
}
__device__ __forceinline__ void cp16(const void* smem_dst, const void* gsrc) {
    unsigned d = (unsigned)__cvta_generic_to_shared(smem_dst);
    asm volatile("cp.async.cg.shared.global [%0], [%1], 16;" :: "r"(d), "l"(gsrc));
}
#define CP_COMMIT() asm volatile("cp.async.commit_group;" ::: "memory")
#define CP_WAIT1()  asm volatile("cp.async.wait_group 1;" ::: "memory")

__device__ __forceinline__ void split_hl(float v, __half& hi, __half& lo) {
    hi = __float2half(v);
    lo = __float2half(v - __half2float(hi));
}
__device__ __forceinline__ void split4(float4 v, __half* h, __half* l) {
    split_hl(v.x, h[0], l[0]); split_hl(v.y, h[1], l[1]);
    split_hl(v.z, h[2], l[2]); split_hl(v.w, h[3], l[3]);
}

// ---------------------------------------------------------------------------
// Split kernels: A rows m-major [hi|lo]; W rows [hi;hi]
// ---------------------------------------------------------------------------
__global__ __launch_bounds__(256) void split_x_kernel(const float* __restrict__ x)
{
    int idx = blockIdx.x * 256 + threadIdx.x;
    int m = idx / (CC / 4);
    int k4 = (idx - m * (CC / 4)) * 4;
    float4 v = *(const float4*)&x[(size_t)m * CC + k4];
    __half hi[4], lo[4];
    split4(v, hi, lo);
    __half* base = g_xs + (size_t)m * K3 + k4;
    *(uint2*)(base)      = *(uint2*)hi;
    *(uint2*)(base + CC) = *(uint2*)lo;
}

__global__ __launch_bounds__(256) void split_wqkv_kernel(const float* __restrict__ w)
{
    int idx = blockIdx.x * 256 + threadIdx.x;
    int k = idx / (C3 / 4);
    int n4 = (idx - k * (C3 / 4)) * 4;
    float4 v = *(const float4*)&w[(size_t)k * C3 + n4];
    __half hi[4];
    hi[0] = __float2half(v.x); hi[1] = __float2half(v.y);
    hi[2] = __float2half(v.z); hi[3] = __float2half(v.w);
    *(uint2*)&g_ws[(size_t)k * C3 + n4]        = *(uint2*)hi;
    *(uint2*)&g_ws[(size_t)(k + CC) * C3 + n4] = *(uint2*)hi;
}

__global__ __launch_bounds__(256) void split_wproj_kernel(const float* __restrict__ w)
{
    int idx = blockIdx.x * 256 + threadIdx.x;
    int k = idx / (CC / 4);
    int n4 = (idx - k * (CC / 4)) * 4;
    float4 v = *(const float4*)&w[(size_t)k * CC + n4];
    __half hi[4];
    hi[0] = __float2half(v.x); hi[1] = __float2half(v.y);
    hi[2] = __float2half(v.z); hi[3] = __float2half(v.w);
    *(uint2*)&g_wps[(size_t)k * CC + n4]        = *(uint2*)hi;
    *(uint2*)&g_wps[(size_t)(k + CC) * CC + n4] = *(uint2*)hi;
}

// Transpose g_yt [b][c][n] f32 -> g_ys [b*N+n][hi|lo over c] fp16
__global__ __launch_bounds__(256) void ysplit_kernel()
{
    __shared__ float sm[32][33];
    const int n0 = blockIdx.x * 32;
    const int c0 = blockIdx.y * 32;
    const int b  = blockIdx.z;
    const int tx = threadIdx.x, ty = threadIdx.y;   // 32 x 8
#pragma unroll
    for (int i = 0; i < 4; i++) {
        int c = c0 + ty + i * 8;
        sm[ty + i * 8][tx] = g_yt[((size_t)b * CC + c) * NN + n0 + tx];
    }
    __syncthreads();
#pragma unroll
    for (int i = 0; i < 4; i++) {
        int n = n0 + ty + i * 8;
        int c = c0 + tx;
        __half hi, lo;
        split_hl(sm[tx][ty + i * 8], hi, lo);
        __half* base = g_ys + ((size_t)b * NN + n) * K3;
        base[c]      = hi;
        base[CC + c] = lo;
    }
}

// ---------------------------------------------------------------------------
// fp16 MMA GEMM: BM=128, BN=128, BK=32. 128 thr = 4 warps (2x2), 64x64 warp
// tile. 3-stage cp.async pipeline (dynamic SMEM), padded layout (R10-proven),
// 2 CTAs/SM. mode 0: scatter q/k/v.  mode 1: out = C + bias.
// Stage layout (halves): As 128x40 = 5120, Bs 32x136 = 4352 -> 9472/stage.
// ---------------------------------------------------------------------------
#define STG_H 9472

__global__ __launch_bounds__(128, 2) void mma_gemm_kernel(
    int Ncols, int mode, const float* __restrict__ bias, float* __restrict__ out)
{
    extern __shared__ __align__(16) __half smp[];
    const __half* __restrict__ A  = mode ? g_ys  : g_xs;
    const __half* __restrict__ Bm = mode ? g_wps : g_ws;

    const int tid = threadIdx.x;
    const int wid = tid >> 5, lane = tid & 31;
    const int rowBase = blockIdx.y * 128;
    const int colBase = blockIdx.x * 128;
    const int warpM = (wid & 1) * 64;
    const int warpN = (wid >> 1) * 64;

    float acc[4][8][4] = {};

    const int ar = tid >> 2, ac = (tid & 3) * 8;      // A: 4 passes (+32 rows)
    const int br = tid >> 4, bc2 = (tid & 15) * 8;    // B: 4 passes (+8 rows)

    const __half* aptr = A  + (size_t)(rowBase + ar) * K3 + ac;
    const __half* bptr = Bm + (size_t)br * Ncols + colBase + bc2;

    const int NT = K3 / 32;

    // prologue: stages 0 and 1
#pragma unroll
    for (int s = 0; s < 2; s++) {
        __half (*As)[40]  = (__half(*)[40]) (smp + s * STG_H);
        __half (*Bs)[136] = (__half(*)[136])(smp + s * STG_H + 5120);
        const int k0 = s * 32;
#pragma unroll
        for (int p = 0; p < 4; p++)
            cp16(&As[ar + p * 32][ac], aptr + (size_t)p * 32 * K3 + k0);
#pragma unroll
        for (int p = 0; p < 4; p++)
            cp16(&Bs[br + p * 8][bc2], bptr + ((size_t)k0 + p * 8) * Ncols);
        CP_COMMIT();
    }

    for (int t = 0; t < NT; t++) {
        CP_WAIT1();            // stage t complete (newest group may be pending)
        __syncthreads();

        if (t + 2 < NT) {      // issue stage t+2 into buffer (t+2)%3
            const int s = (t + 2) % 3;
            __half (*Asn)[40]  = (__half(*)[40]) (smp + s * STG_H);
            __half (*Bsn)[136] = (__half(*)[136])(smp + s * STG_H + 5120);
            const int k0 = (t + 2) * 32;
#pragma unroll
            for (int p = 0; p < 4; p++)
                cp16(&Asn[ar + p * 32][ac], aptr + (size_t)p * 32 * K3 + k0);
#pragma unroll
            for (int p = 0; p < 4; p++)
                cp16(&Bsn[br + p * 8][bc2], bptr + ((size_t)k0 + p * 8) * Ncols);
        }
        CP_COMMIT();           // exactly one group per iteration (empty at tail)

        const int buf = t % 3;
        __half (*As)[40]  = (__half(*)[40]) (smp + buf * STG_H);
        __half (*Bs)[136] = (__half(*)[136])(smp + buf * STG_H + 5120);

#pragma unroll
        for (int ks = 0; ks < 2; ks++) {
            unsigned af[4][4];
#pragma unroll
            for (int im = 0; im < 4; im++)
                ldsm_x4(af[im], &As[warpM + im * 16 + (lane & 15)]
                                   [ks * 16 + (lane >> 4) * 8]);
            unsigned bf[8][2];
#pragma unroll
            for (int g = 0; g < 4; g++) {
                unsigned r[4];
                ldsm_x4_t(r, &Bs[ks * 16 + ((lane >> 3) & 1) * 8 + (lane & 7)]
                             [warpN + g * 16 + (lane >> 4) * 8]);
                bf[2 * g][0] = r[0]; bf[2 * g][1] = r[1];
                bf[2 * g + 1][0] = r[2]; bf[2 * g + 1][1] = r[3];
            }
#pragma unroll
            for (int im = 0; im < 4; im++)
#pragma unroll
                for (int jn = 0; jn < 8; jn++)
                    mma16816(acc[im][jn], af[im], bf[jn]);
        }
    }

    // Epilogue
#pragma unroll
    for (int im = 0; im < 4; im++) {
#pragma unroll
        for (int jn = 0; jn < 8; jn++) {
#pragma unroll
            for (int q = 0; q < 4; q++) {
                int m = warpM + im * 16 + (lane >> 2) + (q >> 1) * 8;
                int n = warpN + jn * 8 + (lane & 3) * 2 + (q & 1);
                float val = acc[im][jn][q];
                int row = rowBase + m;
                int col = colBase + n;
                if (mode == 0) {
                    int b = row >> 12;
                    int nn2 = row & 4095;
                    int h = col / 288;
                    int rem = col - h * 288;
                    int d = rem / 3;
                    int s = rem - d * 3;
                    float* dst = (s == 0) ? g_q : (s == 1) ? g_k : g_v;
                    dst[((b * HH + h) * DD + d) * NN + nn2] = val;
                } else {
                    out[(size_t)row * CC + col] = val + bias[col];
                }
            }
        }
    }
}

// ---------------------------------------------------------------------------
// norm: per-(b,h,d) inverse L2 norm over N for q (y=0) and k (y=1)
// ---------------------------------------------------------------------------
__global__ __launch_bounds__(256) void norm_kernel()
{
    const int row = blockIdx.x;
    const float* src = (blockIdx.y == 0) ? g_q : g_k;
    float*       dst = (blockIdx.y == 0) ? g_rq : g_rk;
    const float* p = src + (size_t)row * NN;
    float s = 0.f;
    for (int i = threadIdx.x; i < NN; i += 256) {
        float v = p[i];
        s = fmaf(v, v, s);
    }
#pragma unroll
    for (int off = 16; off; off >>= 1) s += __shfl_down_sync(0xffffffffu, s, off);
    __shared__ float ws[8];
    if ((threadIdx.x & 31) == 0) ws[threadIdx.x >> 5] = s;
    __syncthreads();
    if (threadIdx.x < 8) {
        float t = ws[threadIdx.x];
#pragma unroll
        for (int off = 4; off; off >>= 1) t += __shfl_down_sync(0xffu, t, off);
        if (threadIdx.x == 0) dst[row] = rsqrtf(t);
    }
}

// ---------------------------------------------------------------------------
// attn_part (tensor MMA): part[sp][bh][d][e] = sum_n q[d,n]k[e,n]
// ---------------------------------------------------------------------------
__global__ __launch_bounds__(128) void attn_part_kernel()
{
    __shared__ __align__(16) __half Qs[2][96][40];
    __shared__ __align__(16) __half Ks[2][96][40];
    const int tid = threadIdx.x;
    const int wid = tid >> 5, lane = tid & 31;
    const int bh = blockIdx.x;
    const int n0 = blockIdx.y * (NN / SPLITS);
    const float* qp = g_q + (size_t)bh * DD * NN;
    const float* kp = g_k + (size_t)bh * DD * NN;
    const int warpM = (wid & 1) * 48, warpN = (wid >> 1) * 48;

    float acc[3][6][4] = {};

    for (int nc = 0; nc < NN / SPLITS; nc += 32) {
        if (nc) __syncthreads();
#pragma unroll
        for (int p = 0; p < 6; p++) {
            int idx = p * 128 + tid;
            int r = idx >> 3, c4 = (idx & 7) * 4;
            float4 qv = *(const float4*)&qp[(size_t)r * NN + n0 + nc + c4];
            float4 kv = *(const float4*)&kp[(size_t)r * NN + n0 + nc + c4];
            __half qh[4], ql[4], kh[4], kl[4];
            split4(qv, qh, ql); split4(kv, kh, kl);
            *(uint2*)&Qs[0][r][c4] = *(uint2*)qh;
            *(uint2*)&Qs[1][r][c4] = *(uint2*)ql;
            *(uint2*)&Ks[0][r][c4] = *(uint2*)kh;
            *(uint2*)&Ks[1][r][c4] = *(uint2*)kl;
        }
        __syncthreads();
#pragma unroll
        for (int term = 0; term < 3; term++) {
            const __half (*Aq)[40] = (term == 1) ? Qs[1] : Qs[0];
            const __half (*Bk)[40] = (term == 2) ? Ks[1] : Ks[0];
#pragma unroll
            for (int ks = 0; ks < 2; ks++) {
                unsigned af[3][4];
#pragma unroll
                for (int im = 0; im < 3; im++)
                    ldsm_x4(af[im], &Aq[warpM + im * 16 + (lane & 15)]
                                       [ks * 16 + (lane >> 4) * 8]);
                unsigned bf[6][2];
#pragma unroll
                for (int jg = 0; jg < 3; jg++) {
                    unsigned r4[4];
                    ldsm_x4(r4, &Bk[warpN + jg * 16 + (lane & 15)]
                                   [ks * 16 + (lane >> 4) * 8]);
                    bf[2 * jg][0] = r4[0]; bf[2 * jg][1] = r4[2];
                    bf[2 * jg + 1][0] = r4[1]; bf[2 * jg + 1][1] = r4[3];
                }
#pragma unroll
                for (int im = 0; im < 3; im++)
#pragma unroll
                    for (int jn = 0; jn < 6; jn++)
                        mma16816(acc[im][jn], af[im], bf[jn]);
            }
        }
    }

    float* dst = g_part + ((size_t)blockIdx.y * BH + bh) * DD * DD;
#pragma unroll
    for (int im = 0; im < 3; im++)
#pragma unroll
        for (int jn = 0; jn < 6; jn++)
#pragma unroll
            for (int q = 0; q < 4; q++) {
                int row = warpM + im * 16 + (lane >> 2) + (q >> 1) * 8;
                int col = warpN + jn * 8 + (lane & 3) * 2 + (q & 1);
                dst[row * DD + col] = acc[im][jn][q];
            }
}

// ---------------------------------------------------------------------------
// softmax: reduce split-K partials, apply norms * temp, softmax over e.
// ---------------------------------------------------------------------------
__global__ __launch_bounds__(128) void softmax_kernel(const float* __restrict__ temp)
{
    const int bhd = blockIdx.x;
    const int bh = bhd / DD;
    const int d  = bhd - bh * DD;
    const int h  = bh & (HH - 1);
    const int e  = threadIdx.x;

    float raw = 0.f;
    float val = -1e30f;
    if (e < DD) {
        float s = 0.f;
#pragma unroll
        for (int sp = 0; sp < SPLITS; sp++)
            s += g_part[(((size_t)sp * BH + bh) * DD + d) * DD + e];
        raw = s * g_rq[bh * DD + d] * g_rk[bh * DD + e] * temp[h];
        val = raw;
    }

    __shared__ float red[128];
    red[e] = val;
    __syncthreads();
#pragma unroll
    for (int off = 64; off >= 1; off >>= 1) {
        if (e < off) red[e] = fmaxf(red[e], red[e + off]);
        __syncthreads();
    }
    float m = red[0];
    __syncthreads();

    float ex = (e < DD) ? expf(raw - m) : 0.f;
    red[e] = ex;
    __syncthreads();
#pragma unroll
    for (int off = 64; off >= 1; off >>= 1) {
        if (e < off) red[e] += red[e + off];
        __syncthreads();
    }
    float sum = red[0];

    if (e < DD)
        g_attn[((size_t)bh * DD + d) * DD + e] = ex / sum;
}

// ---------------------------------------------------------------------------
// av (tensor MMA): y_t[d][n] = sum_e attn[d][e] * v[e][n]
// ---------------------------------------------------------------------------
__global__ __launch_bounds__(128) void av_kernel()
{
    __shared__ __align__(16) __half Ah[2][96][104];
    __shared__ __align__(16) __half Vs[2][16][136];
    const int tid = threadIdx.x;
    const int wid = tid >> 5, lane = tid & 31;
    const int bh = blockIdx.x;
    const int n0 = blockIdx.y * 128;
    const float* ap = g_attn + (size_t)bh * DD * DD;
    const float* vp = g_v + (size_t)bh * DD * NN;
    const int warpM = (wid & 1) * 48, warpN = (wid >> 1) * 64;

    float acc[3][8][4] = {};

#pragma unroll
    for (int p = 0; p < 18; p++) {
        int idx = p * 128 + tid;
        int r = idx / 24, c4 = (idx % 24) * 4;
        float4 v = *(const float4*)&ap[r * DD + c4];
        __half h[4], l[4];
        split4(v, h, l);
        *(uint2*)&Ah[0][r][c4] = *(uint2*)h;
        *(uint2*)&Ah[1][r][c4] = *(uint2*)l;
    }

    for (int ec = 0; ec < DD; ec += 16) {
        __syncthreads();
#pragma unroll
        for (int p = 0; p < 4; p++) {
            int idx = p * 128 + tid;
            int r = idx >> 5, c4 = (idx & 31) * 4;
            float4 vv = *(const float4*)&vp[(size_t)(ec + r) * NN + n0 + c4];
            __half h[4], l[4];
            split4(vv, h, l);
            *(uint2*)&Vs[0][r][c4] = *(uint2*)h;
            *(uint2*)&Vs[1][r][c4] = *(uint2*)l;
        }
        __syncthreads();
#pragma unroll
        for (int term = 0; term < 3; term++) {
            const __half (*Aa)[104] = (term == 1) ? Ah[1] : Ah[0];
            const __half (*Vv)[136] = (term == 2) ? Vs[1] : Vs[0];
            unsigned af[3][4];
#pragma unroll
            for (int im = 0; im < 3; im++)
                ldsm_x4(af[im], &Aa[warpM + im * 16 + (lane & 15)]
                                   [ec + (lane >> 4) * 8]);
            unsigned bf[8][2];
#pragma unroll
            for (int g = 0; g < 4; g++) {
                unsigned r4[4];
                ldsm_x4_t(r4, &Vv[((lane >> 3) & 1) * 8 + (lane & 7)]
                              [warpN + g * 16 + (lane >> 4) * 8]);
                bf[2 * g][0] = r4[0]; bf[2 * g][1] = r4[1];
                bf[2 * g + 1][0] = r4[2]; bf[2 * g + 1][1] = r4[3];
            }
#pragma unroll
            for (int im = 0; im < 3; im++)
#pragma unroll
                for (int jn = 0; jn < 8; jn++)
                    mma16816(acc[im][jn], af[im], bf[jn]);
        }
    }

    float* yp = g_yt + (size_t)bh * DD * NN;
#pragma unroll
    for (int im = 0; im < 3; im++)
#pragma unroll
        for (int jn = 0; jn < 8; jn++)
#pragma unroll
            for (int q = 0; q < 4; q++) {
                int row = warpM + im * 16 + (lane >> 2) + (q >> 1) * 8;
                int col = warpN + jn * 8 + (lane & 3) * 2 + (q & 1);
                yp[(size_t)row * NN + n0 + col] = acc[im][jn][q];
            }
}

// ---------------------------------------------------------------------------
extern "C" void kernel_launch(void* const* d_in, const int* in_sizes, int n_in,
                              void* d_out, int out_size)
{
    const float* x      = (const float*)d_in[0];
    const float* w_qkv  = (const float*)d_in[1];
    const float* w_proj = (const float*)d_in[2];
    const float* b_proj = (const float*)d_in[3];
    const float* temp   = (const float*)d_in[4];
    float* out = (float*)d_out;

    const int gemm_smem = 3 * STG_H * (int)sizeof(__half);   // 56832 B
    cudaFuncSetAttribute(mma_gemm_kernel,
                         cudaFuncAttributeMaxDynamicSharedMemorySize, gemm_smem);

    split_x_kernel<<<(MTOT * CC / 4) / 256, 256>>>(x);
    split_wqkv_kernel<<<(CC * C3 / 4) / 256, 256>>>(w_qkv);
    split_wproj_kernel<<<(CC * CC / 4) / 256, 256>>>(w_proj);

    // GEMM1: scatter q/k/v
    mma_gemm_kernel<<<dim3(C3 / 128, MTOT / 128), 128, gemm_smem>>>(C3, 0, nullptr, nullptr);

    norm_kernel<<<dim3(BH * DD, 2), 256>>>();
    attn_part_kernel<<<dim3(BH, SPLITS), 128>>>();
    softmax_kernel<<<BH * DD, 128>>>(temp);
    av_kernel<<<dim3(BH, NN / 128), 128>>>();

    ysplit_kernel<<<dim3(NN / 32, CC / 32, BB), dim3(32, 8)>>>();

    // GEMM2: out = y @ W_proj + bias
    mma_gemm_kernel<<<dim3(CC / 128, MTOT / 128), 128, gemm_smem>>>(CC, 1, b_proj, out);
}

// round 12
// speedup vs baseline: 1.8766x; 1.0758x over previous
#include <cuda_runtime.h>
#include <cuda_fp16.h>
#include <math.h>

// Problem constants
#define BB 8
#define NN 4096
#define CC 768
#define HH 8
#define DD 96
#define C3 2304
#define BH (BB*HH)
#define SPLITS 8
#define K3 1536   // 2*CC: fp16 split-K depth (A=[hi|lo], B=[hi;hi])
#define MTOT (BB*NN)

// Scratch (device globals — allocation-free kernel_launch)
__device__ float g_q[BB*HH*DD*NN];     // [b][h][d][n]
__device__ float g_k[BB*HH*DD*NN];
__device__ float g_v[BB*HH*DD*NN];
__device__ float g_sq[2*BH*DD];        // sumsq: [0]=q rows, [1]=k rows
__device__ float g_part[SPLITS*BH*DD*DD];
__device__ float g_attn[BH*DD*DD];

// fp16 split operands, M-MAJOR rows: A'[m][k]
__device__ __half g_xs[(size_t)MTOT*K3];    // GEMM1 A': [m][hi|lo]
__device__ __half g_ys[(size_t)MTOT*K3];    // GEMM2 A' (written by av directly)
__device__ __half g_ws[(size_t)K3*C3];      // GEMM1 B': [k][n] rows [hi;hi]
__device__ __half g_wps[(size_t)K3*CC];     // GEMM2 B'

// ---------------------------------------------------------------------------
// MMA / ldmatrix / cp.async helpers
// ---------------------------------------------------------------------------
__device__ __forceinline__ void mma16816(float* c, const unsigned* a, const unsigned* b) {
    asm volatile(
        "mma.sync.aligned.m16n8k16.row.col.f32.f16.f16.f32 "
        "{%0,%1,%2,%3}, {%4,%5,%6,%7}, {%8,%9}, {%0,%1,%2,%3};"
        : "+f"(c[0]), "+f"(c[1]), "+f"(c[2]), "+f"(c[3])
        : "r"(a[0]), "r"(a[1]), "r"(a[2]), "r"(a[3]), "r"(b[0]), "r"(b[1]));
}
__device__ __forceinline__ void ldsm_x4(unsigned* r, const void* p) {
    unsigned addr = (unsigned)__cvta_generic_to_shared(p);
    asm volatile("ldmatrix.sync.aligned.m8n8.x4.shared.b16 {%0,%1,%2,%3}, [%4];"
        : "=r"(r[0]), "=r"(r[1]), "=r"(r[2]), "=r"(r[3]) : "r"(addr));
}
__device__ __forceinline__ void ldsm_x4_t(unsigned* r, const void* p) {
    unsigned addr = (unsigned)__cvta_generic_to_shared(p);
    asm volatile("ldmatrix.sync.aligned.m8n8.x4.trans.shared.b16 {%0,%1,%2,%3}, [%4];"
        : "=r"(r[0]), "=r"(r[1]), "=r"(r[2]), "=r"(r[3]) : "r"(addr));
}
__device__ __forceinline__ void cp16(const void* smem_dst, const void* gsrc) {
    unsigned d = (unsigned)__cvta_generic_to_shared(smem_dst);
    asm volatile("cp.async.cg.shared.global [%0], [%1], 16;" :: "r"(d), "l"(gsrc));
}
#define CP_COMMIT() asm volatile("cp.async.commit_group;" ::: "memory")
#define CP_WAIT2()  asm volatile("cp.async.wait_group 2;" ::: "memory")

__device__ __forceinline__ void split_hl(float v, __half& hi, __half& lo) {
    hi = __float2half(v);
    lo = __float2half(v - __half2float(hi));
}
__device__ __forceinline__ void split4(float4 v, __half* h, __half* l) {
    split_hl(v.x, h[0], l[0]); split_hl(v.y, h[1], l[1]);
    split_hl(v.z, h[2], l[2]); split_hl(v.w, h[3], l[3]);
}

// ---------------------------------------------------------------------------
// Split kernels: A rows m-major [hi|lo]; W rows [hi;hi]
// ---------------------------------------------------------------------------
__global__ __launch_bounds__(256) void split_x_kernel(const float* __restrict__ x)
{
    int idx = blockIdx.x * 256 + threadIdx.x;
    int m = idx / (CC / 4);
    int k4 = (idx - m * (CC / 4)) * 4;
    float4 v = *(const float4*)&x[(size_t)m * CC + k4];
    __half hi[4], lo[4];
    split4(v, hi, lo);
    __half* base = g_xs + (size_t)m * K3 + k4;
    *(uint2*)(base)      = *(uint2*)hi;
    *(uint2*)(base + CC) = *(uint2*)lo;
}

__global__ __launch_bounds__(256) void split_wqkv_kernel(const float* __restrict__ w)
{
    int idx = blockIdx.x * 256 + threadIdx.x;
    int k = idx / (C3 / 4);
    int n4 = (idx - k * (C3 / 4)) * 4;
    float4 v = *(const float4*)&w[(size_t)k * C3 + n4];
    __half hi[4];
    hi[0] = __float2half(v.x); hi[1] = __float2half(v.y);
    hi[2] = __float2half(v.z); hi[3] = __float2half(v.w);
    *(uint2*)&g_ws[(size_t)k * C3 + n4]        = *(uint2*)hi;
    *(uint2*)&g_ws[(size_t)(k + CC) * C3 + n4] = *(uint2*)hi;
}

__global__ __launch_bounds__(256) void split_wproj_kernel(const float* __restrict__ w)
{
    int idx = blockIdx.x * 256 + threadIdx.x;
    int k = idx / (CC / 4);
    int n4 = (idx - k * (CC / 4)) * 4;
    float4 v = *(const float4*)&w[(size_t)k * CC + n4];
    __half hi[4];
    hi[0] = __float2half(v.x); hi[1] = __float2half(v.y);
    hi[2] = __float2half(v.z); hi[3] = __float2half(v.w);
    *(uint2*)&g_wps[(size_t)k * CC + n4]        = *(uint2*)hi;
    *(uint2*)&g_wps[(size_t)(k + CC) * CC + n4] = *(uint2*)hi;
}

// zero g_sq before attn_part accumulation (graph-safe, deterministic)
__global__ __launch_bounds__(256) void zero_sq_kernel()
{
    int i = blockIdx.x * 256 + threadIdx.x;
    if (i < 2 * BH * DD) g_sq[i] = 0.f;
}

// ---------------------------------------------------------------------------
// fp16 MMA GEMM: BM=128, BN=128, BK=32. 128 thr = 4 warps (2x2), 64x64 warp
// tile. 4-stage cp.async pipeline (dynamic SMEM), padded layout, 2 CTAs/SM.
// mode 0: scatter q/k/v.  mode 1: out = C + bias.
// Stage (halves): As 128x40 = 5120, Bs 32x136 = 4352 -> 9472/stage.
// ---------------------------------------------------------------------------
#define STG_H 9472
#define NSTG 4

__global__ __launch_bounds__(128, 2) void mma_gemm_kernel(
    int Ncols, int mode, const float* __restrict__ bias, float* __restrict__ out)
{
    extern __shared__ __align__(16) __half smp[];
    const __half* __restrict__ A  = mode ? g_ys  : g_xs;
    const __half* __restrict__ Bm = mode ? g_wps : g_ws;

    const int tid = threadIdx.x;
    const int wid = tid >> 5, lane = tid & 31;
    const int rowBase = blockIdx.y * 128;
    const int colBase = blockIdx.x * 128;
    const int warpM = (wid & 1) * 64;
    const int warpN = (wid >> 1) * 64;

    float acc[4][8][4] = {};

    const int ar = tid >> 2, ac = (tid & 3) * 8;      // A: 4 passes (+32 rows)
    const int br = tid >> 4, bc2 = (tid & 15) * 8;    // B: 4 passes (+8 rows)

    const __half* aptr = A  + (size_t)(rowBase + ar) * K3 + ac;
    const __half* bptr = Bm + (size_t)br * Ncols + colBase + bc2;

    const int NT = K3 / 32;

    // prologue: stages 0..2
#pragma unroll
    for (int s = 0; s < 3; s++) {
        __half (*As)[40]  = (__half(*)[40]) (smp + s * STG_H);
        __half (*Bs)[136] = (__half(*)[136])(smp + s * STG_H + 5120);
        const int k0 = s * 32;
#pragma unroll
        for (int p = 0; p < 4; p++)
            cp16(&As[ar + p * 32][ac], aptr + (size_t)p * 32 * K3 + k0);
#pragma unroll
        for (int p = 0; p < 4; p++)
            cp16(&Bs[br + p * 8][bc2], bptr + ((size_t)k0 + p * 8) * Ncols);
        CP_COMMIT();
    }

    for (int t = 0; t < NT; t++) {
        CP_WAIT2();            // stage t retired (two newer groups may be pending)
        __syncthreads();

        if (t + 3 < NT) {      // issue stage t+3 into buffer (t+3)%4
            const int s = (t + 3) % NSTG;
            __half (*Asn)[40]  = (__half(*)[40]) (smp + s * STG_H);
            __half (*Bsn)[136] = (__half(*)[136])(smp + s * STG_H + 5120);
            const int k0 = (t + 3) * 32;
#pragma unroll
            for (int p = 0; p < 4; p++)
                cp16(&Asn[ar + p * 32][ac], aptr + (size_t)p * 32 * K3 + k0);
#pragma unroll
            for (int p = 0; p < 4; p++)
                cp16(&Bsn[br + p * 8][bc2], bptr + ((size_t)k0 + p * 8) * Ncols);
        }
        CP_COMMIT();           // exactly one group per iteration (empty at tail)

        const int buf = t % NSTG;
        __half (*As)[40]  = (__half(*)[40]) (smp + buf * STG_H);
        __half (*Bs)[136] = (__half(*)[136])(smp + buf * STG_H + 5120);

#pragma unroll
        for (int ks = 0; ks < 2; ks++) {
            unsigned af[4][4];
#pragma unroll
            for (int im = 0; im < 4; im++)
                ldsm_x4(af[im], &As[warpM + im * 16 + (lane & 15)]
                                   [ks * 16 + (lane >> 4) * 8]);
            unsigned bf[8][2];
#pragma unroll
            for (int g = 0; g < 4; g++) {
                unsigned r[4];
                ldsm_x4_t(r, &Bs[ks * 16 + ((lane >> 3) & 1) * 8 + (lane & 7)]
                             [warpN + g * 16 + (lane >> 4) * 8]);
                bf[2 * g][0] = r[0]; bf[2 * g][1] = r[1];
                bf[2 * g + 1][0] = r[2]; bf[2 * g + 1][1] = r[3];
            }
#pragma unroll
            for (int im = 0; im < 4; im++)
#pragma unroll
                for (int jn = 0; jn < 8; jn++)
                    mma16816(acc[im][jn], af[im], bf[jn]);
        }
    }

    // Epilogue
#pragma unroll
    for (int im = 0; im < 4; im++) {
#pragma unroll
        for (int jn = 0; jn < 8; jn++) {
#pragma unroll
            for (int q = 0; q < 4; q++) {
                int m = warpM + im * 16 + (lane >> 2) + (q >> 1) * 8;
                int n = warpN + jn * 8 + (lane & 3) * 2 + (q & 1);
                float val = acc[im][jn][q];
                int row = rowBase + m;
                int col = colBase + n;
                if (mode == 0) {
                    int b = row >> 12;
                    int nn2 = row & 4095;
                    int h = col / 288;
                    int rem = col - h * 288;
                    int d = rem / 3;
                    int s = rem - d * 3;
                    float* dst = (s == 0) ? g_q : (s == 1) ? g_k : g_v;
                    dst[((b * HH + h) * DD + d) * NN + nn2] = val;
                } else {
                    out[(size_t)row * CC + col] = val + bias[col];
                }
            }
        }
    }
}

// ---------------------------------------------------------------------------
// attn_part (tensor MMA + fused sumsq): part[sp][bh][d][e] = sum_n q[d,n]k[e,n]
// Also accumulates per-row sum(q^2), sum(k^2) into g_sq via atomics.
// ---------------------------------------------------------------------------
__global__ __launch_bounds__(128) void attn_part_kernel()
{
    __shared__ __align__(16) __half Qs[2][96][40];
    __shared__ __align__(16) __half Ks[2][96][40];
    __shared__ float sqs[2][96];
    const int tid = threadIdx.x;
    const int wid = tid >> 5, lane = tid & 31;
    const int bh = blockIdx.x;
    const int n0 = blockIdx.y * (NN / SPLITS);
    const float* qp = g_q + (size_t)bh * DD * NN;
    const float* kp = g_k + (size_t)bh * DD * NN;
    const int warpM = (wid & 1) * 48, warpN = (wid >> 1) * 48;

    if (tid < 96) { sqs[0][tid] = 0.f; sqs[1][tid] = 0.f; }

    float acc[3][6][4] = {};
    float sq_q[6] = {}, sq_k[6] = {};

    for (int nc = 0; nc < NN / SPLITS; nc += 32) {
        if (nc) __syncthreads();
#pragma unroll
        for (int p = 0; p < 6; p++) {
            int idx = p * 128 + tid;
            int r = idx >> 3, c4 = (idx & 7) * 4;
            float4 qv = *(const float4*)&qp[(size_t)r * NN + n0 + nc + c4];
            float4 kv = *(const float4*)&kp[(size_t)r * NN + n0 + nc + c4];
            sq_q[p] = fmaf(qv.x, qv.x, fmaf(qv.y, qv.y, fmaf(qv.z, qv.z, fmaf(qv.w, qv.w, sq_q[p]))));
            sq_k[p] = fmaf(kv.x, kv.x, fmaf(kv.y, kv.y, fmaf(kv.z, kv.z, fmaf(kv.w, kv.w, sq_k[p]))));
            __half qh[4], ql[4], kh[4], kl[4];
            split4(qv, qh, ql); split4(kv, kh, kl);
            *(uint2*)&Qs[0][r][c4] = *(uint2*)qh;
            *(uint2*)&Qs[1][r][c4] = *(uint2*)ql;
            *(uint2*)&Ks[0][r][c4] = *(uint2*)kh;
            *(uint2*)&Ks[1][r][c4] = *(uint2*)kl;
        }
        __syncthreads();
#pragma unroll
        for (int term = 0; term < 3; term++) {
            const __half (*Aq)[40] = (term == 1) ? Qs[1] : Qs[0];
            const __half (*Bk)[40] = (term == 2) ? Ks[1] : Ks[0];
#pragma unroll
            for (int ks = 0; ks < 2; ks++) {
                unsigned af[3][4];
#pragma unroll
                for (int im = 0; im < 3; im++)
                    ldsm_x4(af[im], &Aq[warpM + im * 16 + (lane & 15)]
                                       [ks * 16 + (lane >> 4) * 8]);
                unsigned bf[6][2];
#pragma unroll
                for (int jg = 0; jg < 3; jg++) {
                    unsigned r4[4];
                    ldsm_x4(r4, &Bk[warpN + jg * 16 + (lane & 15)]
                                   [ks * 16 + (lane >> 4) * 8]);
                    bf[2 * jg][0] = r4[0]; bf[2 * jg][1] = r4[2];
                    bf[2 * jg + 1][0] = r4[1]; bf[2 * jg + 1][1] = r4[3];
                }
#pragma unroll
                for (int im = 0; im < 3; im++)
#pragma unroll
                    for (int jn = 0; jn < 6; jn++)
                        mma16816(acc[im][jn], af[im], bf[jn]);
            }
        }
    }

    // fold per-thread sumsq into shared, then global
#pragma unroll
    for (int p = 0; p < 6; p++) {
        int r = (p * 128 + tid) >> 3;
        atomicAdd(&sqs[0][r], sq_q[p]);
        atomicAdd(&sqs[1][r], sq_k[p]);
    }
    __syncthreads();
    if (tid < 96) {
        atomicAdd(&g_sq[bh * DD + tid], sqs[0][tid]);
        atomicAdd(&g_sq[BH * DD + bh * DD + tid], sqs[1][tid]);
    }

    float* dst = g_part + ((size_t)blockIdx.y * BH + bh) * DD * DD;
#pragma unroll
    for (int im = 0; im < 3; im++)
#pragma unroll
        for (int jn = 0; jn < 6; jn++)
#pragma unroll
            for (int q = 0; q < 4; q++) {
                int row = warpM + im * 16 + (lane >> 2) + (q >> 1) * 8;
                int col = warpN + jn * 8 + (lane & 3) * 2 + (q & 1);
                dst[row * DD + col] = acc[im][jn][q];
            }
}

// ---------------------------------------------------------------------------
// softmax: reduce split-K partials, apply rsqrt(sumsq) * temp, softmax over e.
// ---------------------------------------------------------------------------
__global__ __launch_bounds__(128) void softmax_kernel(const float* __restrict__ temp)
{
    const int bhd = blockIdx.x;
    const int bh = bhd / DD;
    const int d  = bhd - bh * DD;
    const int h  = bh & (HH - 1);
    const int e  = threadIdx.x;

    float raw = 0.f;
    float val = -1e30f;
    if (e < DD) {
        float s = 0.f;
#pragma unroll
        for (int sp = 0; sp < SPLITS; sp++)
            s += g_part[(((size_t)sp * BH + bh) * DD + d) * DD + e];
        raw = s * rsqrtf(g_sq[bh * DD + d]) * rsqrtf(g_sq[BH * DD + bh * DD + e]) * temp[h];
        val = raw;
    }

    __shared__ float red[128];
    red[e] = val;
    __syncthreads();
#pragma unroll
    for (int off = 64; off >= 1; off >>= 1) {
        if (e < off) red[e] = fmaxf(red[e], red[e + off]);
        __syncthreads();
    }
    float m = red[0];
    __syncthreads();

    float ex = (e < DD) ? expf(raw - m) : 0.f;
    red[e] = ex;
    __syncthreads();
#pragma unroll
    for (int off = 64; off >= 1; off >>= 1) {
        if (e < off) red[e] += red[e + off];
        __syncthreads();
    }
    float sum = red[0];

    if (e < DD)
        g_attn[((size_t)bh * DD + d) * DD + e] = ex / sum;
}

// ---------------------------------------------------------------------------
// av (tensor MMA, transposed output): C[n][d] = sum_e v[e,n] * attn[d,e],
// written directly into g_ys [b*N+n][h*96+d] as fp16 hi/lo (no yt round-trip).
// A frags = trans-ldsm of Vs[e][n] (reorder r0,r2,r1,r3); B frags = ldsm of
// Ah[d][e]. 4 warps: n in 2x64, d in 2x48.
// ---------------------------------------------------------------------------
__global__ __launch_bounds__(128) void av_kernel()
{
    __shared__ __align__(16) __half Ah[2][96][104];   // attn [d][e] hi/lo
    __shared__ __align__(16) __half Vs[2][16][136];   // v [e][n] hi/lo
    const int tid = threadIdx.x;
    const int wid = tid >> 5, lane = tid & 31;
    const int bh = blockIdx.x;
    const int n0 = blockIdx.y * 128;
    const int b = bh >> 3, h = bh & 7;
    const float* ap = g_attn + (size_t)bh * DD * DD;
    const float* vp = g_v + (size_t)bh * DD * NN;
    const int warpMn = (wid & 1) * 64;    // n rows
    const int warpNd = (wid >> 1) * 48;   // d cols

    float acc[4][6][4] = {};

    // load attn 96x96 once, split
#pragma unroll
    for (int p = 0; p < 18; p++) {
        int idx = p * 128 + tid;
        int r = idx / 24, c4 = (idx % 24) * 4;
        float4 v = *(const float4*)&ap[r * DD + c4];
        __half hh[4], ll[4];
        split4(v, hh, ll);
        *(uint2*)&Ah[0][r][c4] = *(uint2*)hh;
        *(uint2*)&Ah[1][r][c4] = *(uint2*)ll;
    }

    for (int ec = 0; ec < DD; ec += 16) {
        __syncthreads();
#pragma unroll
        for (int p = 0; p < 4; p++) {
            int idx = p * 128 + tid;
            int r = idx >> 5, c4 = (idx & 31) * 4;
            float4 vv = *(const float4*)&vp[(size_t)(ec + r) * NN + n0 + c4];
            __half hh[4], ll[4];
            split4(vv, hh, ll);
            *(uint2*)&Vs[0][r][c4] = *(uint2*)hh;
            *(uint2*)&Vs[1][r][c4] = *(uint2*)ll;
        }
        __syncthreads();
#pragma unroll
        for (int term = 0; term < 3; term++) {
            const __half (*Aa)[104] = (term == 1) ? Ah[1] : Ah[0];   // B operand
            const __half (*Vv)[136] = (term == 2) ? Vs[1] : Vs[0];   // A operand
            unsigned af[4][4];
#pragma unroll
            for (int im = 0; im < 4; im++) {
                unsigned r4[4];
                ldsm_x4_t(r4, &Vv[((lane >> 3) & 1) * 8 + (lane & 7)]
                              [warpMn + im * 16 + (lane >> 4) * 8]);
                af[im][0] = r4[0]; af[im][1] = r4[2];
                af[im][2] = r4[1]; af[im][3] = r4[3];
            }
            unsigned bf[6][2];
#pragma unroll
            for (int jg = 0; jg < 3; jg++) {
                unsigned r4[4];
                ldsm_x4(r4, &Aa[warpNd + jg * 16 + (lane & 15)]
                               [ec + (lane >> 4) * 8]);
                bf[2 * jg][0] = r4[0]; bf[2 * jg][1] = r4[2];
                bf[2 * jg + 1][0] = r4[1]; bf[2 * jg + 1][1] = r4[3];
            }
#pragma unroll
            for (int im = 0; im < 4; im++)
#pragma unroll
                for (int jn = 0; jn < 6; jn++)
                    mma16816(acc[im][jn], af[im], bf[jn]);
        }
    }

    // Epilogue: write g_ys [m = b*N + n][c = h*96+d] hi and lo (+CC)
    __half* ybase = g_ys + ((size_t)b * NN + n0) * K3 + h * DD;
#pragma unroll
    for (int im = 0; im < 4; im++) {
#pragma unroll
        for (int jn = 0; jn < 6; jn++) {
            int rown0 = warpMn + im * 16 + (lane >> 2);
            int cold  = warpNd + jn * 8 + (lane & 3) * 2;
#pragma unroll
            for (int rr = 0; rr < 2; rr++) {
                int rown = rown0 + rr * 8;
                float v0 = acc[im][jn][rr * 2 + 0];
                float v1 = acc[im][jn][rr * 2 + 1];
                __half h0, l0, h1, l1;
                split_hl(v0, h0, l0); split_hl(v1, h1, l1);
                __half* pp = ybase + (size_t)rown * K3 + cold;
                *(__half2*)pp        = __halves2half2(h0, h1);
                *(__half2*)(pp + CC) = __halves2half2(l0, l1);
            }
        }
    }
}

// ---------------------------------------------------------------------------
extern "C" void kernel_launch(void* const* d_in, const int* in_sizes, int n_in,
                              void* d_out, int out_size)
{
    const float* x      = (const float*)d_in[0];
    const float* w_qkv  = (const float*)d_in[1];
    const float* w_proj = (const float*)d_in[2];
    const float* b_proj = (const float*)d_in[3];
    const float* temp   = (const float*)d_in[4];
    float* out = (float*)d_out;

    const int gemm_smem = NSTG * STG_H * (int)sizeof(__half);   // 75776 B
    cudaFuncSetAttribute(mma_gemm_kernel,
                         cudaFuncAttributeMaxDynamicSharedMemorySize, gemm_smem);

    split_x_kernel<<<(MTOT * CC / 4) / 256, 256>>>(x);
    split_wqkv_kernel<<<(CC * C3 / 4) / 256, 256>>>(w_qkv);
    split_wproj_kernel<<<(CC * CC / 4) / 256, 256>>>(w_proj);
    zero_sq_kernel<<<(2 * BH * DD + 255) / 256, 256>>>();

    // GEMM1: scatter q/k/v
    mma_gemm_kernel<<<dim3(C3 / 128, MTOT / 128), 128, gemm_smem>>>(C3, 0, nullptr, nullptr);

    attn_part_kernel<<<dim3(BH, SPLITS), 128>>>();
    softmax_kernel<<<BH * DD, 128>>>(temp);
    av_kernel<<<dim3(BH, NN / 128), 128>>>();

    // GEMM2: out = y @ W_proj + bias
    mma_gemm_kernel<<<dim3(CC / 128, MTOT / 128), 128, gemm_smem>>>(CC, 1, b_proj, out);
}